// round 11
// baseline (speedup 1.0000x reference)
#include <cuda_runtime.h>
#include <cstdint>

#define D_IN  256
#define H_DIM 4096
#define D_OUT 256
#define MAXB  32768

#define MAXC  16
#define DELTA 0.02f      // validated in round 4 for tf32 screen

// ---------------- scratch (no allocations allowed anywhere) ----------------
__device__ float g_GT[H_DIM * D_OUT];
__device__ float g_w2[H_DIM];
__device__ int   g_cnt[MAXB];
__device__ int   g_cand[MAXB][MAXC];
__device__ float g_xt[MAXB * D_IN];    // tf32-rounded x (32 MB)
__device__ float g_wt[H_DIM * D_IN];   // tf32-rounded W (4 MB)

// ---------------- helpers ----------------
__device__ __forceinline__ uint32_t smem_u32(const void* p) {
    uint32_t a;
    asm("{ .reg .u64 t; cvta.to.shared.u64 t, %1; cvt.u32.u64 %0, t; }" : "=r"(a) : "l"(p));
    return a;
}
__device__ __forceinline__ unsigned f2tf(float f) {
    unsigned r; asm("cvt.rna.tf32.f32 %0, %1;" : "=r"(r) : "f"(f)); return r;
}
__device__ __forceinline__ unsigned fkey(float f) {
    unsigned u = __float_as_uint(f);
    return (u & 0x80000000u) ? ~u : (u | 0x80000000u);
}
__device__ __forceinline__ float funkey(unsigned k) {
    return __uint_as_float((k & 0x80000000u) ? (k ^ 0x80000000u) : ~k);
}
__device__ __forceinline__ void mma8(float c[4], const unsigned a[4], const unsigned b[2]) {
    asm volatile("mma.sync.aligned.m16n8k8.row.col.f32.tf32.tf32.f32 "
        "{%0,%1,%2,%3},{%4,%5,%6,%7},{%8,%9},{%0,%1,%2,%3};"
        : "+f"(c[0]), "+f"(c[1]), "+f"(c[2]), "+f"(c[3])
        : "r"(a[0]), "r"(a[1]), "r"(a[2]), "r"(a[3]), "r"(b[0]), "r"(b[1]));
}
#define CP_ASYNC16(dst, src) \
    asm volatile("cp.async.cg.shared.global [%0], [%1], 16;" :: "r"(dst), "l"(src))
#define CP_COMMIT() asm volatile("cp.async.commit_group;" ::: "memory")
#define CP_WAIT0()  asm volatile("cp.async.wait_group 0;" ::: "memory")

// ---------------------------------------------------------------------------
__global__ void zero_cnt_kernel() {
    int i = blockIdx.x * blockDim.x + threadIdx.x;
    if (i < MAXB) g_cnt[i] = 0;
}

// fp32 -> tf32-rounded fp32 (one-time; same rounding as validated round 4)
__global__ void cvt_x_kernel(const float* __restrict__ src, int n4) {
    int i = blockIdx.x * blockDim.x + threadIdx.x;
    if (i >= n4) return;
    float4 v = ((const float4*)src)[i];
    float4 t;
    t.x = __uint_as_float(f2tf(v.x)); t.y = __uint_as_float(f2tf(v.y));
    t.z = __uint_as_float(f2tf(v.z)); t.w = __uint_as_float(f2tf(v.w));
    ((float4*)g_xt)[i] = t;
}
__global__ void cvt_w_kernel(const float* __restrict__ src, int n4) {
    int i = blockIdx.x * blockDim.x + threadIdx.x;
    if (i >= n4) return;
    float4 v = ((const float4*)src)[i];
    float4 t;
    t.x = __uint_as_float(f2tf(v.x)); t.y = __uint_as_float(f2tf(v.y));
    t.z = __uint_as_float(f2tf(v.z)); t.w = __uint_as_float(f2tf(v.w));
    ((float4*)g_wt)[i] = t;
}

// ---------------------------------------------------------------------------
// w2[h]: warp-per-row coalesced stage, lane 0 runs the VALIDATED bit-exact
// sequential chain (k ascending, mul rounded then add).
// ---------------------------------------------------------------------------
__global__ void __launch_bounds__(256) w2_kernel(const float* __restrict__ Wk) {
    __shared__ float buf[8][D_IN];
    int wid = threadIdx.x >> 5, lane = threadIdx.x & 31;
    int h = blockIdx.x * 8 + wid;
    const float4* src = (const float4*)(Wk + h * D_IN);
    float4* d = (float4*)buf[wid];
    d[lane]      = src[lane];
    d[lane + 32] = src[lane + 32];
    __syncwarp();
    if (lane == 0) {
        const float* p = buf[wid];
        float acc = 0.0f;
        for (int k = 0; k < D_IN; k++)
            acc = __fadd_rn(acc, __fmul_rn(p[k], p[k]));
        g_w2[h] = acc;
    }
}

// ---------------------------------------------------------------------------
// Transpose G [D_OUT, H] -> GT [H, D_OUT]
// ---------------------------------------------------------------------------
__global__ void transpose_kernel(const float* __restrict__ G) {
    __shared__ float tile[32][33];
    int h0 = blockIdx.x * 32, d0 = blockIdx.y * 32;
    int tx = threadIdx.x, ty = threadIdx.y;
    #pragma unroll
    for (int j = 0; j < 4; j++)
        tile[ty + j * 8][tx] = G[(d0 + ty + j * 8) * H_DIM + h0 + tx];
    __syncthreads();
    #pragma unroll
    for (int j = 0; j < 4; j++)
        g_GT[(h0 + ty + j * 8) * D_OUT + d0 + tx] = tile[tx][ty + j * 8];
}

// ---------------------------------------------------------------------------
// tf32 screen (validated r8 engine). Grid = 512: blockIdx>>1 selects the
// 128-row m-tile, blockIdx&1 selects the 2048-col H-half. Per-half local
// min screening still yields a provable superset (see analysis); halves
// merge candidates via atomicAdd into g_cnt/g_cand (order-independent).
// ---------------------------------------------------------------------------
#define PITCH   36
#define S_XA0   0
#define S_XA1   18432
#define S_WB0   36864
#define S_WB1   55296
#define S_W2    73728
#define S_SMIN  74240
#define S_CNT   74752
#define S_CAND  75264                 // 128*16*4 = 8192
#define S_TOTAL 83456

__global__ void __launch_bounds__(256, 2) screen_kernel()
{
    extern __shared__ char smem[];
    const uint32_t sb = smem_u32(smem);
    const int tid  = threadIdx.x;
    const int lane = tid & 31, wid = tid >> 5;
    const int wm = wid >> 2, wn = wid & 3;        // 2 x 4 warp grid
    const int gid = lane >> 2, tig = lane & 3;
    const int rowBase = (blockIdx.x >> 1) * 128;
    const int ntBase  = (blockIdx.x & 1) * 16;    // n-tile offset (H half)

    float* w2s = (float*)(smem + S_W2);
    unsigned* smin = (unsigned*)(smem + S_SMIN);
    int* cnt_s = (int*)(smem + S_CNT);
    int (*cand_s)[MAXC] = (int(*)[MAXC])(smem + S_CAND);

    if (tid < 128) { smin[tid] = 0xFFFFFFFFu; cnt_s[tid] = 0; }

    // prologue: tile t=0 (local nt=0, kt=0) into buffer 0
    #pragma unroll
    for (int i = 0; i < 4; i++) {
        int idx = tid + i * 256;
        int r = idx >> 3, kq = idx & 7;
        CP_ASYNC16(sb + S_XA0 + r * 144 + kq * 16, &g_xt[(rowBase + r) * D_IN + kq * 4]);
        CP_ASYNC16(sb + S_WB0 + r * 144 + kq * 16, &g_wt[(ntBase * 128 + r) * D_IN + kq * 4]);
    }
    CP_COMMIT();

    float acc[4][4][4];
    #pragma unroll
    for (int mt = 0; mt < 4; mt++)
        #pragma unroll
        for (int nt = 0; nt < 4; nt++)
            #pragma unroll
            for (int q = 0; q < 4; q++) acc[mt][nt][q] = 0.0f;

    for (int t = 0; t < 128; t++) {               // t = nt_local*8 + kt
        const int nt_g = ntBase + (t >> 3);

        CP_WAIT0();
        __syncthreads();                          // buf t&1 ready; prior compute done

        if ((t & 7) == 0 && tid < 128) w2s[tid] = g_w2[nt_g * 128 + tid];

        // issue loads for step t+1 into the other buffer (overlap compute)
        if (t + 1 < 128) {
            const int t1 = t + 1, nt1 = ntBase + (t1 >> 3), kt1 = t1 & 7;
            const uint32_t xdst = sb + ((t1 & 1) ? S_XA1 : S_XA0);
            const uint32_t wdst = sb + ((t1 & 1) ? S_WB1 : S_WB0);
            #pragma unroll
            for (int i = 0; i < 4; i++) {
                int idx = tid + i * 256;
                int r = idx >> 3, kq = idx & 7;
                CP_ASYNC16(xdst + r * 144 + kq * 16,
                           &g_xt[(rowBase + r) * D_IN + kt1 * 32 + kq * 4]);
                CP_ASYNC16(wdst + r * 144 + kq * 16,
                           &g_wt[(nt1 * 128 + r) * D_IN + kt1 * 32 + kq * 4]);
            }
        }
        CP_COMMIT();

        // ---- compute on buffer t&1 (identical math to validated round 4/8) ----
        const float* xa = (const float*)(smem + ((t & 1) ? S_XA1 : S_XA0));
        const float* wb = (const float*)(smem + ((t & 1) ? S_WB1 : S_WB0));
        #pragma unroll
        for (int ks = 0; ks < 4; ks++) {
            const int kk = ks * 8;
            unsigned a[4][4], b[4][2];
            #pragma unroll
            for (int mt = 0; mt < 4; mt++) {
                int r0 = wm * 64 + mt * 16 + gid;
                a[mt][0] = __float_as_uint(xa[r0 * PITCH + kk + tig]);
                a[mt][1] = __float_as_uint(xa[(r0 + 8) * PITCH + kk + tig]);
                a[mt][2] = __float_as_uint(xa[r0 * PITCH + kk + tig + 4]);
                a[mt][3] = __float_as_uint(xa[(r0 + 8) * PITCH + kk + tig + 4]);
            }
            #pragma unroll
            for (int nt = 0; nt < 4; nt++) {
                int c0 = wn * 32 + nt * 8 + gid;
                b[nt][0] = __float_as_uint(wb[c0 * PITCH + kk + tig]);
                b[nt][1] = __float_as_uint(wb[c0 * PITCH + kk + tig + 4]);
            }
            #pragma unroll
            for (int mt = 0; mt < 4; mt++)
                #pragma unroll
                for (int nt = 0; nt < 4; nt++)
                    mma8(acc[mt][nt], a[mt], b[nt]);
        }

        if ((t & 7) == 7) {
            // ---- epilogue (validated round-4 two-pass) ----
            const int n0 = nt_g * 128;
            float w2v[4][2];
            #pragma unroll
            for (int nt = 0; nt < 4; nt++) {
                w2v[nt][0] = w2s[wn * 32 + nt * 8 + 2 * tig];
                w2v[nt][1] = w2s[wn * 32 + nt * 8 + 2 * tig + 1];
            }
            float m8v[4][2];
            #pragma unroll
            for (int mt = 0; mt < 4; mt++) {
                #pragma unroll
                for (int h = 0; h < 2; h++) {
                    int lr = wm * 64 + mt * 16 + gid + h * 8;
                    float m8 = 3.4e38f;
                    #pragma unroll
                    for (int nt = 0; nt < 4; nt++)
                        #pragma unroll
                        for (int p = 0; p < 2; p++)
                            m8 = fminf(m8, fmaf(-2.0f, acc[mt][nt][h * 2 + p], w2v[nt][p]));
                    m8 = fminf(m8, __shfl_xor_sync(0xffffffffu, m8, 1));
                    m8 = fminf(m8, __shfl_xor_sync(0xffffffffu, m8, 2));
                    m8v[mt][h] = m8;
                    if (tig == 0) atomicMin(&smin[lr], fkey(m8));
                }
            }
            __syncthreads();
            #pragma unroll
            for (int mt = 0; mt < 4; mt++) {
                #pragma unroll
                for (int h = 0; h < 2; h++) {
                    int lr = wm * 64 + mt * 16 + gid + h * 8;
                    float thr = funkey(smin[lr]) + DELTA;
                    if (m8v[mt][h] < thr) {       // usually skipped
                        #pragma unroll
                        for (int nt = 0; nt < 4; nt++)
                            #pragma unroll
                            for (int p = 0; p < 2; p++) {
                                float s = fmaf(-2.0f, acc[mt][nt][h * 2 + p], w2v[nt][p]);
                                if (s < thr) {
                                    int colg = n0 + wn * 32 + nt * 8 + 2 * tig + p;
                                    int pos = atomicAdd(&cnt_s[lr], 1);
                                    if (pos < MAXC) cand_s[lr][pos] = colg;
                                }
                            }
                    }
                }
            }
            #pragma unroll
            for (int mt = 0; mt < 4; mt++)
                #pragma unroll
                for (int nt = 0; nt < 4; nt++)
                    #pragma unroll
                    for (int q = 0; q < 4; q++) acc[mt][nt][q] = 0.0f;
        }
    }

    __syncthreads();
    // merge this half's candidates into the global per-row lists
    if (tid < 128) {
        int b = rowBase + tid;
        int c = cnt_s[tid];
        if (c > 0) {
            int base = atomicAdd(&g_cnt[b], c);   // true count (uncapped)
            int cc = c < MAXC ? c : MAXC;
            for (int i = 0; i < cc; i++) {
                int pos = base + i;
                if (pos < MAXC) g_cand[b][pos] = cand_s[tid][i];
            }
        }
    }
}

// ---------------------------------------------------------------------------
// Exact rescore (VALIDATED bit-exact recipe) + fused gather of the winner's
// grossberg column (and winner index as float).
// ---------------------------------------------------------------------------
__device__ __forceinline__ float exact_score(
    const float* __restrict__ xsh, const float* __restrict__ wrow,
    float x2v, float w2v)
{
    float acc = 0.0f;
    const float4* w4 = (const float4*)wrow;
    #pragma unroll 4
    for (int k4 = 0; k4 < D_IN / 4; k4++) {
        float4 wv = w4[k4];
        const float* xp = xsh + k4 * 4;
        acc = __fmaf_rn(xp[0], wv.x, acc);
        acc = __fmaf_rn(xp[1], wv.y, acc);
        acc = __fmaf_rn(xp[2], wv.z, acc);
        acc = __fmaf_rn(xp[3], wv.w, acc);
    }
    float t = __fadd_rn(x2v, -__fmul_rn(2.0f, acc));
    return __fadd_rn(t, w2v);
}

__global__ void __launch_bounds__(256) rescore_gather_kernel(
    const float* __restrict__ x, const float* __restrict__ Wk,
    float* __restrict__ out, int writeWin, int winOffset)
{
    __shared__ float xsh[8][D_IN];
    int wid = threadIdx.x >> 5, lane = threadIdx.x & 31;
    int b = blockIdx.x * 8 + wid;

    const float4* xr = (const float4*)(x + b * D_IN);
    float4* xd = (float4*)xsh[wid];
    xd[lane]      = xr[lane];
    xd[lane + 32] = xr[lane + 32];
    __syncwarp();

    float x2v = 0.0f;
    if (lane == 0) {
        const float* xp = xsh[wid];
        for (int k = 0; k < D_IN; k++)
            x2v = __fadd_rn(x2v, __fmul_rn(xp[k], xp[k]));
    }
    x2v = __shfl_sync(0xffffffffu, x2v, 0);

    int cnt = g_cnt[b];
    float bv = 3.4e38f;
    int   bi = 0x7FFFFFFF;

    if (cnt <= MAXC) {
        if (lane < cnt) {
            int h = g_cand[b][lane];
            bv = exact_score(xsh[wid], Wk + h * D_IN, x2v, g_w2[h]);
            bi = h;
        }
    } else {
        for (int h = lane; h < H_DIM; h += 32) {
            float s = exact_score(xsh[wid], Wk + h * D_IN, x2v, g_w2[h]);
            if (s < bv) { bv = s; bi = h; }
        }
    }
    #pragma unroll
    for (int off = 16; off > 0; off >>= 1) {
        float ov = __shfl_down_sync(0xffffffffu, bv, off);
        int   oi = __shfl_down_sync(0xffffffffu, bi, off);
        if (ov < bv || (ov == bv && oi < bi)) { bv = ov; bi = oi; }
    }
    int w = __shfl_sync(0xffffffffu, bi, 0);

    // fused gather: out[b,:] = GT[w,:]
    const float4* gt = (const float4*)&g_GT[w * D_OUT];
    float4* od = (float4*)&out[b * D_OUT];
    od[lane]      = gt[lane];
    od[lane + 32] = gt[lane + 32];
    if (writeWin && lane == 0) out[winOffset + b] = (float)w;
}

__global__ void win_only_kernel(float* __restrict__ out,
                                const float* __restrict__ x,
                                const float* __restrict__ Wk, int B) {
    // (kept for the index-only output shape; uses candidates too)
    int b = blockIdx.x * blockDim.x + threadIdx.x;
    if (b >= B) return;
    // sequential exact fallback per row over candidates
    float x2v = 0.0f;
    const float* xp = x + b * D_IN;
    for (int k = 0; k < D_IN; k++)
        x2v = __fadd_rn(x2v, __fmul_rn(xp[k], xp[k]));
    int cnt = g_cnt[b];
    float bv = 3.4e38f; int bi = 0;
    int lim = cnt <= MAXC ? cnt : 0;
    if (lim == 0 && cnt > MAXC) {
        for (int h = 0; h < H_DIM; h++) {
            float s = exact_score(xp, Wk + h * D_IN, x2v, g_w2[h]);
            if (s < bv) { bv = s; bi = h; }
        }
    } else {
        for (int i = 0; i < lim; i++) {
            int h = g_cand[b][i];
            float s = exact_score(xp, Wk + h * D_IN, x2v, g_w2[h]);
            if (s < bv || (s == bv && h < bi)) { bv = s; bi = h; }
        }
    }
    out[b] = (float)bi;
}

// ---------------------------------------------------------------------------
extern "C" void kernel_launch(void* const* d_in, const int* in_sizes, int n_in,
                              void* d_out, int out_size) {
    const float* x  = (const float*)d_in[0];
    const float* Wk = (const float*)d_in[1];
    const float* G  = (const float*)d_in[2];
    float* out = (float*)d_out;
    int B = in_sizes[0] / D_IN;   // 32768

    cudaFuncSetAttribute(screen_kernel,
                         cudaFuncAttributeMaxDynamicSharedMemorySize, S_TOTAL);

    zero_cnt_kernel<<<MAXB / 256, 256>>>();
    cvt_x_kernel<<<(B * D_IN / 4 + 255) / 256, 256>>>(x, B * D_IN / 4);
    cvt_w_kernel<<<(H_DIM * D_IN / 4 + 255) / 256, 256>>>(Wk, H_DIM * D_IN / 4);
    w2_kernel<<<H_DIM / 8, 256>>>(Wk);
    transpose_kernel<<<dim3(H_DIM / 32, D_OUT / 32), dim3(32, 8)>>>(G);
    screen_kernel<<<(B / 128) * 2, 256, S_TOTAL>>>();

    if (out_size >= B * D_OUT) {
        int writeWin = (out_size >= B * D_OUT + B) ? 1 : 0;
        rescore_gather_kernel<<<B / 8, 256>>>(x, Wk, out, writeWin, B * D_OUT);
    } else {
        win_only_kernel<<<(B + 255) / 256, 256>>>(out, x, Wk, B);
    }
}

// round 12
// speedup vs baseline: 2.4116x; 2.4116x over previous
#include <cuda_runtime.h>
#include <cstdint>

#define D_IN  256
#define H_DIM 4096
#define D_OUT 256
#define MAXB  32768

#define MAXC  32
#define DELTA 0.05f      // covers tf32 screen error with truncated (raw fp32) A operand

// ---------------- scratch (no allocations allowed anywhere) ----------------
__device__ float g_GT[H_DIM * D_OUT];
__device__ float g_w2[H_DIM];
__device__ int   g_cnt[MAXB];
__device__ int   g_cand[MAXB][MAXC];
__device__ float g_wt[H_DIM * D_IN];   // tf32-rounded W (4 MB)

// ---------------- helpers ----------------
__device__ __forceinline__ uint32_t smem_u32(const void* p) {
    uint32_t a;
    asm("{ .reg .u64 t; cvta.to.shared.u64 t, %1; cvt.u32.u64 %0, t; }" : "=r"(a) : "l"(p));
    return a;
}
__device__ __forceinline__ unsigned f2tf(float f) {
    unsigned r; asm("cvt.rna.tf32.f32 %0, %1;" : "=r"(r) : "f"(f)); return r;
}
__device__ __forceinline__ unsigned fkey(float f) {
    unsigned u = __float_as_uint(f);
    return (u & 0x80000000u) ? ~u : (u | 0x80000000u);
}
__device__ __forceinline__ float funkey(unsigned k) {
    return __uint_as_float((k & 0x80000000u) ? (k ^ 0x80000000u) : ~k);
}
__device__ __forceinline__ void mma8(float c[4], const unsigned a[4], const unsigned b[2]) {
    asm volatile("mma.sync.aligned.m16n8k8.row.col.f32.tf32.tf32.f32 "
        "{%0,%1,%2,%3},{%4,%5,%6,%7},{%8,%9},{%0,%1,%2,%3};"
        : "+f"(c[0]), "+f"(c[1]), "+f"(c[2]), "+f"(c[3])
        : "r"(a[0]), "r"(a[1]), "r"(a[2]), "r"(a[3]), "r"(b[0]), "r"(b[1]));
}
#define CP_ASYNC16(dst, src) \
    asm volatile("cp.async.cg.shared.global [%0], [%1], 16;" :: "r"(dst), "l"(src))
#define CP_COMMIT() asm volatile("cp.async.commit_group;" ::: "memory")
#define CP_WAIT0()  asm volatile("cp.async.wait_group 0;" ::: "memory")

// ---------------------------------------------------------------------------
// fp32 -> tf32-rounded fp32 for W only (one-time, 4 MB)
// ---------------------------------------------------------------------------
__global__ void cvt_w_kernel(const float* __restrict__ src, int n4) {
    int i = blockIdx.x * blockDim.x + threadIdx.x;
    if (i >= n4) return;
    float4 v = ((const float4*)src)[i];
    float4 t;
    t.x = __uint_as_float(f2tf(v.x)); t.y = __uint_as_float(f2tf(v.y));
    t.z = __uint_as_float(f2tf(v.z)); t.w = __uint_as_float(f2tf(v.w));
    ((float4*)g_wt)[i] = t;
}

// ---------------------------------------------------------------------------
// w2[h]: warp-per-row coalesced stage, lane 0 runs the VALIDATED bit-exact
// sequential chain (k ascending, mul rounded then add).
// ---------------------------------------------------------------------------
__global__ void __launch_bounds__(256) w2_kernel(const float* __restrict__ Wk) {
    __shared__ float buf[8][D_IN];
    int wid = threadIdx.x >> 5, lane = threadIdx.x & 31;
    int h = blockIdx.x * 8 + wid;
    const float4* src = (const float4*)(Wk + h * D_IN);
    float4* d = (float4*)buf[wid];
    d[lane]      = src[lane];
    d[lane + 32] = src[lane + 32];
    __syncwarp();
    if (lane == 0) {
        const float* p = buf[wid];
        float acc = 0.0f;
        for (int k = 0; k < D_IN; k++)
            acc = __fadd_rn(acc, __fmul_rn(p[k], p[k]));
        g_w2[h] = acc;
    }
}

// ---------------------------------------------------------------------------
// Transpose G [D_OUT, H] -> GT [H, D_OUT]
// ---------------------------------------------------------------------------
__global__ void transpose_kernel(const float* __restrict__ G) {
    __shared__ float tile[32][33];
    int h0 = blockIdx.x * 32, d0 = blockIdx.y * 32;
    int tx = threadIdx.x, ty = threadIdx.y;
    #pragma unroll
    for (int j = 0; j < 4; j++)
        tile[ty + j * 8][tx] = G[(d0 + ty + j * 8) * H_DIM + h0 + tx];
    __syncthreads();
    #pragma unroll
    for (int j = 0; j < 4; j++)
        g_GT[(h0 + ty + j * 8) * D_OUT + d0 + tx] = tile[tx][ty + j * 8];
}

// ---------------------------------------------------------------------------
// tf32 screen — the validated r8 engine, unchanged except: A streams RAW x
// (hardware-truncated to tf32 inside mma; DELTA widened accordingly).
// CTA = 128 rows; 32 n-tiles x 8 k-tiles = 256 pipeline steps.
// ---------------------------------------------------------------------------
#define PITCH   36
#define S_XA0   0
#define S_XA1   18432
#define S_WB0   36864
#define S_WB1   55296
#define S_W2    73728
#define S_SMIN  74240
#define S_CNT   74752
#define S_CAND  75264                 // 128*32*4 = 16384
#define S_TOTAL 91648

__global__ void __launch_bounds__(256, 2) screen_kernel(const float* __restrict__ x)
{
    extern __shared__ char smem[];
    const uint32_t sb = smem_u32(smem);
    const int tid  = threadIdx.x;
    const int lane = tid & 31, wid = tid >> 5;
    const int wm = wid >> 2, wn = wid & 3;        // 2 x 4 warp grid
    const int gid = lane >> 2, tig = lane & 3;
    const int rowBase = blockIdx.x * 128;

    float* w2s = (float*)(smem + S_W2);
    unsigned* smin = (unsigned*)(smem + S_SMIN);
    int* cnt_s = (int*)(smem + S_CNT);
    int (*cand_s)[MAXC] = (int(*)[MAXC])(smem + S_CAND);

    if (tid < 128) { smin[tid] = 0xFFFFFFFFu; cnt_s[tid] = 0; }

    // prologue: tile t=0 (nt=0, kt=0) into buffer 0
    #pragma unroll
    for (int i = 0; i < 4; i++) {
        int idx = tid + i * 256;
        int r = idx >> 3, kq = idx & 7;
        CP_ASYNC16(sb + S_XA0 + r * 144 + kq * 16, &x[(rowBase + r) * D_IN + kq * 4]);
        CP_ASYNC16(sb + S_WB0 + r * 144 + kq * 16, &g_wt[r * D_IN + kq * 4]);
    }
    CP_COMMIT();

    float acc[4][4][4];
    #pragma unroll
    for (int mt = 0; mt < 4; mt++)
        #pragma unroll
        for (int nt = 0; nt < 4; nt++)
            #pragma unroll
            for (int q = 0; q < 4; q++) acc[mt][nt][q] = 0.0f;

    for (int t = 0; t < 256; t++) {               // t = nt*8 + kt
        const int nt_tile = t >> 3;

        CP_WAIT0();
        __syncthreads();                          // buf t&1 ready; prior compute done

        if ((t & 7) == 0 && tid < 128) w2s[tid] = g_w2[nt_tile * 128 + tid];

        // issue loads for step t+1 into the other buffer (overlap compute)
        if (t + 1 < 256) {
            const int t1 = t + 1, nt1 = t1 >> 3, kt1 = t1 & 7;
            const uint32_t xdst = sb + ((t1 & 1) ? S_XA1 : S_XA0);
            const uint32_t wdst = sb + ((t1 & 1) ? S_WB1 : S_WB0);
            #pragma unroll
            for (int i = 0; i < 4; i++) {
                int idx = tid + i * 256;
                int r = idx >> 3, kq = idx & 7;
                CP_ASYNC16(xdst + r * 144 + kq * 16,
                           &x[(rowBase + r) * D_IN + kt1 * 32 + kq * 4]);
                CP_ASYNC16(wdst + r * 144 + kq * 16,
                           &g_wt[(nt1 * 128 + r) * D_IN + kt1 * 32 + kq * 4]);
            }
        }
        CP_COMMIT();

        // ---- compute on buffer t&1 ----
        const float* xa = (const float*)(smem + ((t & 1) ? S_XA1 : S_XA0));
        const float* wb = (const float*)(smem + ((t & 1) ? S_WB1 : S_WB0));
        #pragma unroll
        for (int ks = 0; ks < 4; ks++) {
            const int kk = ks * 8;
            unsigned a[4][4], b[4][2];
            #pragma unroll
            for (int mt = 0; mt < 4; mt++) {
                int r0 = wm * 64 + mt * 16 + gid;
                a[mt][0] = __float_as_uint(xa[r0 * PITCH + kk + tig]);
                a[mt][1] = __float_as_uint(xa[(r0 + 8) * PITCH + kk + tig]);
                a[mt][2] = __float_as_uint(xa[r0 * PITCH + kk + tig + 4]);
                a[mt][3] = __float_as_uint(xa[(r0 + 8) * PITCH + kk + tig + 4]);
            }
            #pragma unroll
            for (int nt = 0; nt < 4; nt++) {
                int c0 = wn * 32 + nt * 8 + gid;
                b[nt][0] = __float_as_uint(wb[c0 * PITCH + kk + tig]);
                b[nt][1] = __float_as_uint(wb[c0 * PITCH + kk + tig + 4]);
            }
            #pragma unroll
            for (int mt = 0; mt < 4; mt++)
                #pragma unroll
                for (int nt = 0; nt < 4; nt++)
                    mma8(acc[mt][nt], a[mt], b[nt]);
        }

        if ((t & 7) == 7) {
            // ---- epilogue (validated two-pass) ----
            const int n0 = nt_tile * 128;
            float w2v[4][2];
            #pragma unroll
            for (int nt = 0; nt < 4; nt++) {
                w2v[nt][0] = w2s[wn * 32 + nt * 8 + 2 * tig];
                w2v[nt][1] = w2s[wn * 32 + nt * 8 + 2 * tig + 1];
            }
            float m8v[4][2];
            #pragma unroll
            for (int mt = 0; mt < 4; mt++) {
                #pragma unroll
                for (int h = 0; h < 2; h++) {
                    int lr = wm * 64 + mt * 16 + gid + h * 8;
                    float m8 = 3.4e38f;
                    #pragma unroll
                    for (int nt = 0; nt < 4; nt++)
                        #pragma unroll
                        for (int p = 0; p < 2; p++)
                            m8 = fminf(m8, fmaf(-2.0f, acc[mt][nt][h * 2 + p], w2v[nt][p]));
                    m8 = fminf(m8, __shfl_xor_sync(0xffffffffu, m8, 1));
                    m8 = fminf(m8, __shfl_xor_sync(0xffffffffu, m8, 2));
                    m8v[mt][h] = m8;
                    if (tig == 0) atomicMin(&smin[lr], fkey(m8));
                }
            }
            __syncthreads();
            #pragma unroll
            for (int mt = 0; mt < 4; mt++) {
                #pragma unroll
                for (int h = 0; h < 2; h++) {
                    int lr = wm * 64 + mt * 16 + gid + h * 8;
                    float thr = funkey(smin[lr]) + DELTA;
                    if (m8v[mt][h] < thr) {       // usually skipped
                        #pragma unroll
                        for (int nt = 0; nt < 4; nt++)
                            #pragma unroll
                            for (int p = 0; p < 2; p++) {
                                float s = fmaf(-2.0f, acc[mt][nt][h * 2 + p], w2v[nt][p]);
                                if (s < thr) {
                                    int colg = n0 + wn * 32 + nt * 8 + 2 * tig + p;
                                    int pos = atomicAdd(&cnt_s[lr], 1);
                                    if (pos < MAXC) cand_s[lr][pos] = colg;
                                }
                            }
                    }
                }
            }
            #pragma unroll
            for (int mt = 0; mt < 4; mt++)
                #pragma unroll
                for (int nt = 0; nt < 4; nt++)
                    #pragma unroll
                    for (int q = 0; q < 4; q++) acc[mt][nt][q] = 0.0f;
        }
    }

    __syncthreads();
    if (tid < 128) {
        int b = rowBase + tid;
        int c = cnt_s[tid];
        g_cnt[b] = c;
        int cc = c < MAXC ? c : MAXC;
        for (int i = 0; i < cc; i++) g_cand[b][i] = cand_s[tid][i];
    }
}

// ---------------------------------------------------------------------------
// Exact rescore (VALIDATED bit-exact recipe) fused with the winner gather.
// ---------------------------------------------------------------------------
__device__ __forceinline__ float exact_score(
    const float* __restrict__ xsh, const float* __restrict__ wrow,
    float x2v, float w2v)
{
    float acc = 0.0f;
    const float4* w4 = (const float4*)wrow;
    #pragma unroll 4
    for (int k4 = 0; k4 < D_IN / 4; k4++) {
        float4 wv = w4[k4];
        const float* xp = xsh + k4 * 4;
        acc = __fmaf_rn(xp[0], wv.x, acc);
        acc = __fmaf_rn(xp[1], wv.y, acc);
        acc = __fmaf_rn(xp[2], wv.z, acc);
        acc = __fmaf_rn(xp[3], wv.w, acc);
    }
    float t = __fadd_rn(x2v, -__fmul_rn(2.0f, acc));
    return __fadd_rn(t, w2v);
}

__global__ void __launch_bounds__(256) rescore_gather_kernel(
    const float* __restrict__ x, const float* __restrict__ Wk,
    float* __restrict__ out, int writeWin, int winOffset)
{
    __shared__ float xsh[8][D_IN];
    int wid = threadIdx.x >> 5, lane = threadIdx.x & 31;
    int b = blockIdx.x * 8 + wid;

    const float4* xr = (const float4*)(x + b * D_IN);
    float4* xd = (float4*)xsh[wid];
    xd[lane]      = xr[lane];
    xd[lane + 32] = xr[lane + 32];
    __syncwarp();

    float x2v = 0.0f;
    if (lane == 0) {
        const float* xp = xsh[wid];
        for (int k = 0; k < D_IN; k++)
            x2v = __fadd_rn(x2v, __fmul_rn(xp[k], xp[k]));
    }
    x2v = __shfl_sync(0xffffffffu, x2v, 0);

    int cnt = g_cnt[b];
    float bv = 3.4e38f;
    int   bi = 0x7FFFFFFF;

    if (cnt <= MAXC) {
        if (lane < cnt) {
            int h = g_cand[b][lane];
            bv = exact_score(xsh[wid], Wk + h * D_IN, x2v, g_w2[h]);
            bi = h;
        }
    } else {
        for (int h = lane; h < H_DIM; h += 32) {
            float s = exact_score(xsh[wid], Wk + h * D_IN, x2v, g_w2[h]);
            if (s < bv) { bv = s; bi = h; }
        }
    }
    #pragma unroll
    for (int off = 16; off > 0; off >>= 1) {
        float ov = __shfl_down_sync(0xffffffffu, bv, off);
        int   oi = __shfl_down_sync(0xffffffffu, bi, off);
        if (ov < bv || (ov == bv && oi < bi)) { bv = ov; bi = oi; }
    }
    int w = __shfl_sync(0xffffffffu, bi, 0);

    // fused gather: out[b,:] = GT[w,:]
    const float4* gt = (const float4*)&g_GT[w * D_OUT];
    float4* od = (float4*)&out[b * D_OUT];
    od[lane]      = gt[lane];
    od[lane + 32] = gt[lane + 32];
    if (writeWin && lane == 0) out[winOffset + b] = (float)w;
}

__global__ void win_only_kernel(float* __restrict__ out,
                                const float* __restrict__ x,
                                const float* __restrict__ Wk, int B) {
    int b = blockIdx.x * blockDim.x + threadIdx.x;
    if (b >= B) return;
    float x2v = 0.0f;
    const float* xp = x + b * D_IN;
    for (int k = 0; k < D_IN; k++)
        x2v = __fadd_rn(x2v, __fmul_rn(xp[k], xp[k]));
    int cnt = g_cnt[b];
    float bv = 3.4e38f; int bi = 0;
    if (cnt > MAXC) {
        for (int h = 0; h < H_DIM; h++) {
            float s = exact_score(xp, Wk + h * D_IN, x2v, g_w2[h]);
            if (s < bv) { bv = s; bi = h; }
        }
    } else {
        for (int i = 0; i < cnt; i++) {
            int h = g_cand[b][i];
            float s = exact_score(xp, Wk + h * D_IN, x2v, g_w2[h]);
            if (s < bv || (s == bv && h < bi)) { bv = s; bi = h; }
        }
    }
    out[b] = (float)bi;
}

// ---------------------------------------------------------------------------
extern "C" void kernel_launch(void* const* d_in, const int* in_sizes, int n_in,
                              void* d_out, int out_size) {
    const float* x  = (const float*)d_in[0];
    const float* Wk = (const float*)d_in[1];
    const float* G  = (const float*)d_in[2];
    float* out = (float*)d_out;
    int B = in_sizes[0] / D_IN;   // 32768

    cudaFuncSetAttribute(screen_kernel,
                         cudaFuncAttributeMaxDynamicSharedMemorySize, S_TOTAL);

    cvt_w_kernel<<<(H_DIM * D_IN / 4 + 255) / 256, 256>>>(Wk, H_DIM * D_IN / 4);
    w2_kernel<<<H_DIM / 8, 256>>>(Wk);
    transpose_kernel<<<dim3(H_DIM / 32, D_OUT / 32), dim3(32, 8)>>>(G);
    screen_kernel<<<B / 128, 256, S_TOTAL>>>(x);

    if (out_size >= B * D_OUT) {
        int writeWin = (out_size >= B * D_OUT + B) ? 1 : 0;
        rescore_gather_kernel<<<B / 8, 256>>>(x, Wk, out, writeWin, B * D_OUT);
    } else {
        win_only_kernel<<<(B + 255) / 256, 256>>>(out, x, Wk, B);
    }
}